// round 6
// baseline (speedup 1.0000x reference)
#include <cuda_runtime.h>
#include <stdint.h>

// out[r, :] = sum over edges (r, c) of weight[c, :]
// adj: [2, nnz] (rows then cols), dtype int64 OR int32 (runtime-detected)
// weight: [size, 256] float32
// out: [size, 256] float32

#define OUTF 256          // out_features (fixed by the problem)
#define THREADS_PER_EDGE 64   // 64 threads * float4 = 256 floats
#define EDGES_PER_BLOCK 4     // blockDim = 256

__device__ int g_adj_is64;

// Deterministic dtype sniff: real int64 indices are all in [0, nrows).
// If the buffer is actually int32 pairs, reading them as int64 yields
// huge values (high word = next random index, ~never 0 for 64 samples).
__global__ void detect_dtype_kernel(const long long* __restrict__ adj,
                                    long long nrows, int n_check) {
    if (blockIdx.x == 0 && threadIdx.x == 0) {
        int is64 = 1;
        for (int i = 0; i < n_check; i++) {
            long long v = adj[i];
            if (v < 0 || v >= nrows) { is64 = 0; break; }
        }
        g_adj_is64 = is64;
    }
}

__global__ void zero_kernel(float4* __restrict__ out, long long n4) {
    long long i = (long long)blockIdx.x * blockDim.x + threadIdx.x;
    long long stride = (long long)gridDim.x * blockDim.x;
    float4 z = make_float4(0.f, 0.f, 0.f, 0.f);
    for (; i < n4; i += stride) out[i] = z;
}

__global__ void __launch_bounds__(THREADS_PER_EDGE * EDGES_PER_BLOCK)
scatter_kernel(const void* __restrict__ adj,
               const float* __restrict__ weight,
               float* __restrict__ out,
               int nnz) {
    int edge = blockIdx.x * EDGES_PER_BLOCK + (threadIdx.x >> 6);
    int t = threadIdx.x & (THREADS_PER_EDGE - 1);
    if (edge >= nnz) return;

    long long r, c;
    if (g_adj_is64) {
        const long long* a = (const long long*)adj;
        r = a[edge];
        c = a[nnz + edge];
    } else {
        const int* a = (const int*)adj;
        r = (long long)a[edge];
        c = (long long)a[nnz + edge];
    }

    // Coalesced 1KB read of weight row c (64 threads x float4)
    const float4 v = __ldg((const float4*)(weight + c * OUTF) + t);

    // Coalesced atomics into out row r (duplicate rows are rare but exist)
    float* o = out + r * OUTF + (long long)t * 4;
    atomicAdd(o + 0, v.x);
    atomicAdd(o + 1, v.y);
    atomicAdd(o + 2, v.z);
    atomicAdd(o + 3, v.w);
}

extern "C" void kernel_launch(void* const* d_in, const int* in_sizes, int n_in,
                              void* d_out, int out_size) {
    // Input order per reference: adj [2, nnz], size (scalar, unused), weight [size, 256]
    const void* adj = d_in[0];
    const float* weight = (const float*)d_in[2];
    float* out = (float*)d_out;

    int nnz = in_sizes[0] / 2;
    long long nrows = (long long)out_size / OUTF;

    // 1) detect adj dtype (int64 vs silently-downcast int32)
    int n_check = nnz < 64 ? nnz : 64;
    detect_dtype_kernel<<<1, 32>>>((const long long*)adj, nrows, n_check);

    // 2) zero the output
    long long n4 = (long long)out_size / 4;
    int zthreads = 256;
    long long zblocks_ll = (n4 + zthreads - 1) / zthreads;
    int zblocks = (int)(zblocks_ll > 65535 * 16 ? 65535 * 16 : zblocks_ll);
    if (zblocks < 1) zblocks = 1;
    zero_kernel<<<zblocks, zthreads>>>((float4*)out, n4);

    // 3) scatter-add: 4 edges per 256-thread block
    int sblocks = (nnz + EDGES_PER_BLOCK - 1) / EDGES_PER_BLOCK;
    if (sblocks < 1) sblocks = 1;
    scatter_kernel<<<sblocks, THREADS_PER_EDGE * EDGES_PER_BLOCK>>>(
        adj, weight, out, nnz);
}

// round 7
// speedup vs baseline: 1.6018x; 1.6018x over previous
#include <cuda_runtime.h>
#include <stdint.h>

// out[r, :] = sum over edges (r, c) of weight[c, :]
// adj: [2, nnz] (rows then cols), dtype int64 OR int32 (runtime-detected)
// weight: [size, 256] float32 ; out: [size, 256] float32
//
// Strategy: build CSR (counting sort) in __device__ scratch, then a pure
// gather-sum kernel: no output zeroing pass, no float atomics (the L2
// atomic ALU was the 74us bottleneck in the scatter version).

#define OUTF 256
#define MAXN   (1 << 17)   // max rows   (problem: 100000)
#define MAXNNZ (1 << 17)   // max edges  (problem: 100000)
#define SCAN_BLOCKS 256
#define SCAN_THREADS 256

__device__ int g_adj_is64;
__device__ int g_count[MAXN];
__device__ int g_rowptr[MAXN + 1];
__device__ int g_cursor[MAXN];
__device__ int g_cols[MAXNNZ];
__device__ int g_chunk_sums[SCAN_BLOCKS];
__device__ int g_chunk_offsets[SCAN_BLOCKS];

// ---------------------------------------------------------------- helpers
__device__ __forceinline__ int edge_row(const void* adj, int e, int nnz) {
    if (g_adj_is64) return (int)((const long long*)adj)[e];
    return ((const int*)adj)[e];
}
__device__ __forceinline__ int edge_col(const void* adj, int e, int nnz) {
    if (g_adj_is64) return (int)((const long long*)adj)[nnz + e];
    return ((const int*)adj)[nnz + e];
}

// ------------------------------------------------- K1: init + dtype sniff
__global__ void init_kernel(const long long* __restrict__ adj,
                            long long nrows, int n_check, int n) {
    int i = blockIdx.x * blockDim.x + threadIdx.x;
    int stride = gridDim.x * blockDim.x;
    for (; i < n; i += stride) g_count[i] = 0;
    if (blockIdx.x == 0 && threadIdx.x == 0) {
        // int64 indices are all in [0, nrows); int32-pairs read as int64 are
        // huge/negative with overwhelming probability over 64 samples.
        int is64 = 1;
        for (int k = 0; k < n_check; k++) {
            long long v = adj[k];
            if (v < 0 || v >= nrows) { is64 = 0; break; }
        }
        g_adj_is64 = is64;
    }
}

// ------------------------------------------------------ K2: row histogram
__global__ void hist_kernel(const void* __restrict__ adj, int nnz) {
    int e = blockIdx.x * blockDim.x + threadIdx.x;
    if (e >= nnz) return;
    atomicAdd(&g_count[edge_row(adj, e, nnz)], 1);
}

// ------------------------------------------------- K3a: per-chunk totals
__global__ void scan1_kernel(int n, int chunk) {
    __shared__ int sh[SCAN_THREADS];
    int b = blockIdx.x, t = threadIdx.x;
    int lo = b * chunk;
    int hi = min(lo + chunk, n);
    int s = 0;
    for (int i = lo + t; i < hi; i += SCAN_THREADS) s += g_count[i];
    sh[t] = s;
    __syncthreads();
    for (int off = SCAN_THREADS >> 1; off > 0; off >>= 1) {
        if (t < off) sh[t] += sh[t + off];
        __syncthreads();
    }
    if (t == 0) g_chunk_sums[b] = sh[0];
}

// ----------------------------------------- K3b: scan chunk totals (1 blk)
__global__ void scan2_kernel(int n) {
    __shared__ int sh[SCAN_BLOCKS];
    int t = threadIdx.x;
    int v = g_chunk_sums[t];
    sh[t] = v;
    __syncthreads();
    for (int off = 1; off < SCAN_BLOCKS; off <<= 1) {
        int x = (t >= off) ? sh[t - off] : 0;
        __syncthreads();
        sh[t] += x;
        __syncthreads();
    }
    g_chunk_offsets[t] = sh[t] - v;            // exclusive
    if (t == SCAN_BLOCKS - 1) g_rowptr[n] = sh[t];  // total = nnz
}

// --------------------------------- K3c: per-chunk exclusive scan + cursor
__global__ void scan3_kernel(int n, int chunk) {
    __shared__ int sh[SCAN_THREADS];
    int b = blockIdx.x, t = threadIdx.x;
    int lo = b * chunk;
    int hi = min(lo + chunk, n);
    int running = g_chunk_offsets[b];
    for (int base = lo; base < hi; base += SCAN_THREADS) {
        int i = base + t;
        int v = (i < hi) ? g_count[i] : 0;
        sh[t] = v;
        __syncthreads();
        for (int off = 1; off < SCAN_THREADS; off <<= 1) {
            int x = (t >= off) ? sh[t - off] : 0;
            __syncthreads();
            sh[t] += x;
            __syncthreads();
        }
        if (i < hi) {
            int excl = running + sh[t] - v;
            g_rowptr[i] = excl;
            g_cursor[i] = excl;
        }
        running += sh[SCAN_THREADS - 1];
        __syncthreads();
    }
}

// ------------------------------------------------------- K4: bucket fill
__global__ void fill_kernel(const void* __restrict__ adj, int nnz) {
    int e = blockIdx.x * blockDim.x + threadIdx.x;
    if (e >= nnz) return;
    int r = edge_row(adj, e, nnz);
    int c = edge_col(adj, e, nnz);
    int pos = atomicAdd(&g_cursor[r], 1);
    g_cols[pos] = c;
}

// -------------------------------------------------------- K5: gather-sum
// 64 threads per row (64 x float4 = 256 floats), 4 rows per 256-thr block.
__global__ void __launch_bounds__(256)
gather_kernel(const float* __restrict__ weight,
              float* __restrict__ out, int n) {
    int row = blockIdx.x * 4 + (threadIdx.x >> 6);
    int t = threadIdx.x & 63;
    if (row >= n) return;
    int beg = g_rowptr[row];
    int end = g_rowptr[row + 1];
    float4 acc = make_float4(0.f, 0.f, 0.f, 0.f);
    for (int e = beg; e < end; e++) {
        int c = g_cols[e];   // broadcast across the 64-thread group
        float4 v = __ldg((const float4*)(weight + (long long)c * OUTF) + t);
        acc.x += v.x; acc.y += v.y; acc.z += v.z; acc.w += v.w;
    }
    *((float4*)(out + (long long)row * OUTF) + t) = acc;
}

// --------------------------------------------- fallback (capacity exceed)
__global__ void zero_kernel(float4* __restrict__ out, long long n4) {
    long long i = (long long)blockIdx.x * blockDim.x + threadIdx.x;
    long long stride = (long long)gridDim.x * blockDim.x;
    float4 z = make_float4(0.f, 0.f, 0.f, 0.f);
    for (; i < n4; i += stride) out[i] = z;
}
__global__ void __launch_bounds__(256)
scatter_kernel(const void* __restrict__ adj,
               const float* __restrict__ weight,
               float* __restrict__ out, int nnz) {
    int edge = blockIdx.x * 4 + (threadIdx.x >> 6);
    int t = threadIdx.x & 63;
    if (edge >= nnz) return;
    long long r = edge_row(adj, edge, nnz);
    long long c = edge_col(adj, edge, nnz);
    float4 v = __ldg((const float4*)(weight + c * OUTF) + t);
    float* o = out + r * OUTF + (long long)t * 4;
    atomicAdd(o + 0, v.x);
    atomicAdd(o + 1, v.y);
    atomicAdd(o + 2, v.z);
    atomicAdd(o + 3, v.w);
}

extern "C" void kernel_launch(void* const* d_in, const int* in_sizes, int n_in,
                              void* d_out, int out_size) {
    const void* adj = d_in[0];
    const float* weight = (const float*)d_in[2];
    float* out = (float*)d_out;

    int nnz = in_sizes[0] / 2;
    int n = out_size / OUTF;

    int n_check = nnz < 64 ? nnz : 64;

    if (n <= MAXN && nnz <= MAXNNZ) {
        // --- CSR pipeline ---
        int chunk = (n + SCAN_BLOCKS - 1) / SCAN_BLOCKS;
        int eblocks = (nnz + 255) / 256;

        init_kernel<<<128, 256>>>((const long long*)adj, (long long)n,
                                  n_check, n);
        hist_kernel<<<eblocks, 256>>>(adj, nnz);
        scan1_kernel<<<SCAN_BLOCKS, SCAN_THREADS>>>(n, chunk);
        scan2_kernel<<<1, SCAN_BLOCKS>>>(n);
        scan3_kernel<<<SCAN_BLOCKS, SCAN_THREADS>>>(n, chunk);
        fill_kernel<<<eblocks, 256>>>(adj, nnz);
        gather_kernel<<<(n + 3) / 4, 256>>>(weight, out, n);
    } else {
        // --- fallback: atomic scatter (round-5 path) ---
        init_kernel<<<1, 32>>>((const long long*)adj, (long long)n, n_check, 0);
        long long n4 = (long long)out_size / 4;
        int zblocks = (int)((n4 + 255) / 256);
        if (zblocks < 1) zblocks = 1;
        zero_kernel<<<zblocks, 256>>>((float4*)out, n4);
        int sblocks = (nnz + 3) / 4;
        if (sblocks < 1) sblocks = 1;
        scatter_kernel<<<sblocks, 256>>>(adj, weight, out, nnz);
    }
}